// round 2
// baseline (speedup 1.0000x reference)
#include <cuda_runtime.h>
#include <cuda_bf16.h>
#include <cstdint>

#define EPS 1e-15f

// ---------------- scratch buffers (no runtime allocation allowed) ----------
__device__ float g_qkv[(size_t)4 * 1536 * 4096];   // 100.7 MB
__device__ float g_agg[(size_t)4 * 1536 * 4096];   // 100.7 MB
__device__ float g_attn[(size_t)4 * 1024 * 4096];  //  67.1 MB

// ---------------------------------------------------------------------------
// SGEMM: C[b] = A (MxK, row-major) * B[b] (KxN row-major), N = 4096 fixed.
// Optional residual add (Res has same layout as C).
// Tiles: 128x128x16, 256 threads, 8x8 per-thread microtile.
// grid.x = M/128, grid.y = 4 batches * 32 N-tiles = 128
// ---------------------------------------------------------------------------
template <bool RES>
__global__ __launch_bounds__(256) void sgemm128(
    const float* __restrict__ A, const float* __restrict__ B,
    const float* __restrict__ Res, float* __restrict__ C, int M, int K) {
  const int N = 4096;
  const int mBase = blockIdx.x * 128;
  const int bn = blockIdx.y;
  const int batch = bn >> 5;
  const int nBase = (bn & 31) * 128;

  const float* Bp = B + (size_t)batch * K * N;
  float* Cp = C + (size_t)batch * M * N;

  __shared__ float As[16][128];
  __shared__ float Bs[16][128];

  const int tid = threadIdx.x;
  const int ty = tid >> 4;   // 0..15
  const int tx = tid & 15;   // 0..15

  float acc[8][8];
#pragma unroll
  for (int i = 0; i < 8; i++)
#pragma unroll
    for (int j = 0; j < 8; j++) acc[i][j] = 0.f;

  // A loads: 128 rows x 16 cols = 512 float4; 2 per thread
  const int aRow = tid >> 2;         // 0..63
  const int aCol = (tid & 3) * 4;    // 0,4,8,12
  // B loads: 16 rows x 128 cols = 512 float4; 2 per thread
  const int bRow = tid >> 5;         // 0..7
  const int bCol = (tid & 31) * 4;   // 0..124

  for (int k0 = 0; k0 < K; k0 += 16) {
    float4 a0 = *(const float4*)(A + (size_t)(mBase + aRow) * K + k0 + aCol);
    float4 a1 = *(const float4*)(A + (size_t)(mBase + aRow + 64) * K + k0 + aCol);
    float4 b0 = *(const float4*)(Bp + (size_t)(k0 + bRow) * N + nBase + bCol);
    float4 b1 = *(const float4*)(Bp + (size_t)(k0 + bRow + 8) * N + nBase + bCol);

    As[aCol + 0][aRow] = a0.x;
    As[aCol + 1][aRow] = a0.y;
    As[aCol + 2][aRow] = a0.z;
    As[aCol + 3][aRow] = a0.w;
    As[aCol + 0][aRow + 64] = a1.x;
    As[aCol + 1][aRow + 64] = a1.y;
    As[aCol + 2][aRow + 64] = a1.z;
    As[aCol + 3][aRow + 64] = a1.w;
    *(float4*)&Bs[bRow][bCol] = b0;
    *(float4*)&Bs[bRow + 8][bCol] = b1;
    __syncthreads();

#pragma unroll
    for (int k = 0; k < 16; k++) {
      float ra[8], rb[8];
#pragma unroll
      for (int i = 0; i < 8; i++) ra[i] = As[k][ty * 8 + i];
#pragma unroll
      for (int j = 0; j < 8; j++) rb[j] = Bs[k][tx * 8 + j];
#pragma unroll
      for (int i = 0; i < 8; i++)
#pragma unroll
        for (int j = 0; j < 8; j++) acc[i][j] += ra[i] * rb[j];
    }
    __syncthreads();
  }

#pragma unroll
  for (int i = 0; i < 8; i++) {
    const int row = mBase + ty * 8 + i;
    float* cdst = Cp + (size_t)row * N + nBase + tx * 8;
#pragma unroll
    for (int j = 0; j < 8; j += 4) {
      float4 v = make_float4(acc[i][j], acc[i][j + 1], acc[i][j + 2], acc[i][j + 3]);
      if (RES) {
        const float* rsrc = Res + (size_t)batch * M * N + (size_t)row * N + nBase + tx * 8;
        float4 r = *(const float4*)(rsrc + j);
        v.x += r.x; v.y += r.y; v.z += r.z; v.w += r.w;
      }
      *(float4*)(cdst + j) = v;
    }
  }
}

// ---------------------------------------------------------------------------
// Fused depthwise 5x5 (pad 2) + grouped 1x1 (192 groups, 8 in -> 8 out).
// grid: (192 groups, 4 row-tiles of 16, 4 batches), 256 threads.
// Loads the 8 input planes' tile+halo into smem, computes per-pixel dw[8]
// into registers, applies the 8x8 pw matrix, stores agg. dw never hits HBM.
// ---------------------------------------------------------------------------
__global__ __launch_bounds__(256) void dwpw_kernel(
    const float* __restrict__ qkv, const float* __restrict__ w_dw,
    const float* __restrict__ w_pw, float* __restrict__ agg) {
  const int g = blockIdx.x;
  const int r0 = blockIdx.y * 16;
  const int b = blockIdx.z;
  const int tid = threadIdx.x;

  __shared__ float tile[8][20][68];  // 8 ch, 16+4 rows, 64+4 cols
  __shared__ float wd[8][25];
  __shared__ float wp[64];

  if (tid < 200) {
    int i = tid / 25, t = tid % 25;
    wd[i][t] = w_dw[(size_t)(g * 8 + i) * 25 + t];
  }
  if (tid < 64) wp[tid] = w_pw[(size_t)g * 64 + tid];

  const float* src = qkv + (size_t)(b * 1536 + g * 8) * 4096;
  for (int e = tid; e < 8 * 20 * 68; e += 256) {
    int i = e / (20 * 68);
    int rem = e - i * (20 * 68);
    int ry = rem / 68;
    int rx = rem - ry * 68;
    int gy = r0 + ry - 2;
    int gx = rx - 2;
    float v = 0.f;
    if (gy >= 0 && gy < 64 && gx >= 0 && gx < 64)
      v = src[(size_t)i * 4096 + gy * 64 + gx];
    tile[i][ry][rx] = v;
  }
  __syncthreads();

  float* dst = agg + (size_t)(b * 1536 + g * 8) * 4096;
  for (int p = tid; p < 1024; p += 256) {
    int py = p >> 6;
    int px = p & 63;
    float dwv[8];
#pragma unroll
    for (int i = 0; i < 8; i++) {
      float s = 0.f;
#pragma unroll
      for (int ky = 0; ky < 5; ky++)
#pragma unroll
        for (int kx = 0; kx < 5; kx++)
          s += tile[i][py + ky][px + kx] * wd[i][ky * 5 + kx];
      dwv[i] = s;
    }
    const int off = (r0 + py) * 64 + px;
#pragma unroll
    for (int o = 0; o < 8; o++) {
      float a = 0.f;
#pragma unroll
      for (int i = 0; i < 8; i++) a += wp[o * 8 + i] * dwv[i];
      dst[(size_t)o * 4096 + off] = a;
    }
  }
}

// ---------------------------------------------------------------------------
// Linear attention per head. One block per (b, h); 512 blocks, 256 threads.
// Head h (0..127): channels 24h..24h+23 of the [qkv ; agg] concat:
//   h < 64 -> qkv buffer at channel 24h; h >= 64 -> agg at channel 24(h-64).
// Phase 1: vk[d][e] = sum_n v[d,n]*relu(k[e,n])  (d=8 row: v==1)
// Phase 2: out[d,n] = (sum_e vk[d][e]*relu(q[e,n])) / (row8 + EPS)
// ---------------------------------------------------------------------------
__global__ __launch_bounds__(256) void attn_kernel(
    const float* __restrict__ qkv, const float* __restrict__ agg,
    float* __restrict__ attn) {
  const int bh = blockIdx.x;
  const int b = bh >> 7;
  const int h = bh & 127;
  const float* base = (h < 64)
      ? qkv + (size_t)(b * 1536 + h * 24) * 4096
      : agg + (size_t)(b * 1536 + (h - 64) * 24) * 4096;
  const float* qp = base;
  const float* kp = base + (size_t)8 * 4096;
  const float* vp = base + (size_t)16 * 4096;

  __shared__ float svk[72];
  const int tid = threadIdx.x;
  if (tid < 72) svk[tid] = 0.f;
  __syncthreads();

  float a[72];
#pragma unroll
  for (int t = 0; t < 72; t++) a[t] = 0.f;

  for (int n = tid; n < 4096; n += 256) {
    float kv[8], vv[8];
#pragma unroll
    for (int e = 0; e < 8; e++) kv[e] = fmaxf(kp[(size_t)e * 4096 + n], 0.f);
#pragma unroll
    for (int d = 0; d < 8; d++) vv[d] = vp[(size_t)d * 4096 + n];
#pragma unroll
    for (int d = 0; d < 8; d++)
#pragma unroll
      for (int e = 0; e < 8; e++) a[d * 8 + e] += vv[d] * kv[e];
#pragma unroll
    for (int e = 0; e < 8; e++) a[64 + e] += kv[e];
  }

#pragma unroll
  for (int t = 0; t < 72; t++) {
    float s = a[t];
    s += __shfl_down_sync(0xffffffffu, s, 16);
    s += __shfl_down_sync(0xffffffffu, s, 8);
    s += __shfl_down_sync(0xffffffffu, s, 4);
    s += __shfl_down_sync(0xffffffffu, s, 2);
    s += __shfl_down_sync(0xffffffffu, s, 1);
    if ((tid & 31) == 0) atomicAdd(&svk[t], s);
  }
  __syncthreads();

  float vk[72];
#pragma unroll
  for (int t = 0; t < 72; t++) vk[t] = svk[t];

  float* op = attn + (size_t)(b * 1024 + h * 8) * 4096;
  for (int n = tid; n < 4096; n += 256) {
    float qv[8];
#pragma unroll
    for (int e = 0; e < 8; e++) qv[e] = fmaxf(qp[(size_t)e * 4096 + n], 0.f);
    float den = EPS;
#pragma unroll
    for (int e = 0; e < 8; e++) den += vk[64 + e] * qv[e];
    float rden = 1.0f / den;
#pragma unroll
    for (int d = 0; d < 8; d++) {
      float num = 0.f;
#pragma unroll
      for (int e = 0; e < 8; e++) num += vk[d * 8 + e] * qv[e];
      op[(size_t)d * 4096 + n] = num * rden;
    }
  }
}

// ---------------------------------------------------------------------------
extern "C" void kernel_launch(void* const* d_in, const int* in_sizes, int n_in,
                              void* d_out, int out_size) {
  const float* x      = (const float*)d_in[0];
  const float* w_qkv  = (const float*)d_in[1];
  const float* w_dw   = (const float*)d_in[2];
  const float* w_pw   = (const float*)d_in[3];
  const float* w_proj = (const float*)d_in[4];
  float* out = (float*)d_out;

  float *qkv, *agg, *attn;
  cudaGetSymbolAddress((void**)&qkv, g_qkv);
  cudaGetSymbolAddress((void**)&agg, g_agg);
  cudaGetSymbolAddress((void**)&attn, g_attn);

  // 1) qkv = w_qkv (1536x512) @ x (per batch 512x4096)
  sgemm128<false><<<dim3(12, 128), 256>>>(w_qkv, x, nullptr, qkv, 1536, 512);
  // 2) agg = grouped_pw(depthwise5x5(qkv))
  dwpw_kernel<<<dim3(192, 4, 4), 256>>>(qkv, w_dw, w_pw, agg);
  // 3) linear attention -> attn (B,1024,4096)
  attn_kernel<<<512, 256>>>(qkv, agg, attn);
  // 4) out = x + w_proj (512x1024) @ attn
  sgemm128<true><<<dim3(4, 128), 256>>>(w_proj, attn, x, out, 512, 1024);
}

// round 6
// speedup vs baseline: 1.8447x; 1.8447x over previous
#include <cuda_runtime.h>
#include <cuda_bf16.h>
#include <cstdint>

#define EPS 1e-15f

// ---------------- scratch buffers (no runtime allocation allowed) ----------
__device__ float g_qkv[(size_t)4 * 1536 * 4096];          // fp32 qkv
__device__ float g_agg[(size_t)4 * 1536 * 4096];          // fp32 agg
__device__ __nv_bfloat16 g_xt_h[(size_t)4 * 4096 * 512];  // x transposed, hi
__device__ __nv_bfloat16 g_xt_l[(size_t)4 * 4096 * 512];  // x transposed, lo
__device__ __nv_bfloat16 g_at_h[(size_t)4 * 4096 * 1024]; // attn transposed, hi
__device__ __nv_bfloat16 g_at_l[(size_t)4 * 4096 * 1024]; // attn transposed, lo
__device__ __nv_bfloat16 g_wq_h[1536 * 512];
__device__ __nv_bfloat16 g_wq_l[1536 * 512];
__device__ __nv_bfloat16 g_wp_h[512 * 1024];
__device__ __nv_bfloat16 g_wp_l[512 * 1024];

// ---------------- PTX helpers (base-target-safe: HMMA/ldmatrix/cp.async) ----
__device__ __forceinline__ uint32_t smem_u32(const void* p) {
  uint32_t a;
  asm("{ .reg .u64 t; cvta.to.shared.u64 t, %1; cvt.u32.u64 %0, t; }"
      : "=r"(a) : "l"(p));
  return a;
}

__device__ __forceinline__ void cp_async16(uint32_t saddr, const void* gptr) {
  asm volatile("cp.async.cg.shared.global [%0], [%1], 16;" ::
               "r"(saddr), "l"(gptr));
}
__device__ __forceinline__ void cp_commit() {
  asm volatile("cp.async.commit_group;");
}
__device__ __forceinline__ void cp_wait_all() {
  asm volatile("cp.async.wait_group 0;");
}

__device__ __forceinline__ void ldsm4(uint32_t* r, uint32_t addr) {
  asm volatile("ldmatrix.sync.aligned.m8n8.x4.shared.b16 {%0,%1,%2,%3}, [%4];"
               : "=r"(r[0]), "=r"(r[1]), "=r"(r[2]), "=r"(r[3]) : "r"(addr));
}

__device__ __forceinline__ void mma_bf16(float* d, const uint32_t* a,
                                         const uint32_t* b) {
  asm volatile(
      "mma.sync.aligned.m16n8k16.row.col.f32.bf16.bf16.f32 "
      "{%0,%1,%2,%3}, {%4,%5,%6,%7}, {%8,%9}, {%0,%1,%2,%3};"
      : "+f"(d[0]), "+f"(d[1]), "+f"(d[2]), "+f"(d[3])
      : "r"(a[0]), "r"(a[1]), "r"(a[2]), "r"(a[3]), "r"(b[0]), "r"(b[1]));
}

// ---------------------------------------------------------------------------
// bf16x3 split GEMM on HMMA (mma.sync m16n8k16).
// C[b] (M x 4096 fp32) = A (M x K) * Bt[b]^T, A = Ah+Al, Bt = Bh+Bl,
// product = Ah*Bh + Ah*Bl + Al*Bh (fp32 accumulate).
// A row-major [M][K]; Bt stored [4096][K] (K contiguous).
// CTA tile 128x128, K-chunk 64, double-buffered cp.async smem.
// 8 warps: 2 (M) x 4 (N); warp tile 64x32.
// ---------------------------------------------------------------------------
#define STAGE_BYTES 65536
#define GEMM_SMEM_BYTES (2 * STAGE_BYTES)

template <bool RES>
__global__ void __launch_bounds__(256, 1) gemm_hmma(
    const __nv_bfloat16* __restrict__ Ah, const __nv_bfloat16* __restrict__ Al,
    const __nv_bfloat16* __restrict__ Bh, const __nv_bfloat16* __restrict__ Bl,
    const float* __restrict__ Res, float* __restrict__ C, int M, int K) {
  extern __shared__ char smem[];
  const uint32_t sbase = smem_u32(smem);

  const int tid = threadIdx.x;
  const int warp = tid >> 5;
  const int lane = tid & 31;
  const int wm = warp >> 2;        // 0..1 (M)
  const int wn = warp & 3;         // 0..3 (N)
  const int m0 = blockIdx.x * 128;
  const int n0 = blockIdx.y * 128;
  const int b = blockIdx.z;
  const int NB = 4096;

  const __nv_bfloat16* Bhb = Bh + (size_t)b * NB * K;
  const __nv_bfloat16* Blb = Bl + (size_t)b * NB * K;

  float acc[4][4][4];
#pragma unroll
  for (int i = 0; i < 4; i++)
#pragma unroll
    for (int j = 0; j < 4; j++)
#pragma unroll
      for (int r = 0; r < 4; r++) acc[i][j][r] = 0.f;

  const int nch = K >> 6;

  // ---- stage loader: 4 tiles (Ah,Al,Bh,Bl), 128 rows x 8 chunks of 16B ----
  const int lrow0 = tid >> 3;      // +32*i
  const int lc = tid & 7;          // chunk 0..7
  auto load_stage = [&](int ch, int s) {
    const int k0 = ch << 6;
    const uint32_t sb = sbase + (uint32_t)s * STAGE_BYTES;
#pragma unroll
    for (int i = 0; i < 4; i++) {
      const int row = lrow0 + 32 * i;
      const uint32_t soff =
          (uint32_t)row * 128u + (uint32_t)((lc ^ (row & 7)) << 4);
      const size_t ga = (size_t)(m0 + row) * K + k0 + lc * 8;
      const size_t gb = (size_t)(n0 + row) * K + k0 + lc * 8;
      cp_async16(sb + 0u * 16384u + soff, Ah + ga);
      cp_async16(sb + 1u * 16384u + soff, Al + ga);
      cp_async16(sb + 2u * 16384u + soff, Bhb + gb);
      cp_async16(sb + 3u * 16384u + soff, Blb + gb);
    }
    cp_commit();
  };

  load_stage(0, 0);

  // ldmatrix lane geometry (same for A and B, all non-transposed):
  // lanes 0-15 -> rows 0-15 (k-half 0), lanes 16-31 -> rows 0-15 (k-half 1)
  const int lr = lane & 15;
  const int kh = lane >> 4;

  for (int ch = 0; ch < nch; ch++) {
    cp_wait_all();
    __syncthreads();
    if (ch + 1 < nch) load_stage(ch + 1, (ch + 1) & 1);

    const uint32_t sb = sbase + (uint32_t)(ch & 1) * STAGE_BYTES;
    const uint32_t sAh = sb, sAl = sb + 16384u;
    const uint32_t sBh = sb + 32768u, sBl = sb + 49152u;

#pragma unroll
    for (int s = 0; s < 4; s++) {
      const int chunk = 2 * s + kh;
      uint32_t ah[4][4], al[4][4];
#pragma unroll
      for (int mt = 0; mt < 4; mt++) {
        const int row = wm * 64 + mt * 16 + lr;
        const uint32_t off =
            (uint32_t)row * 128u + (uint32_t)((chunk ^ (row & 7)) << 4);
        ldsm4(ah[mt], sAh + off);
        ldsm4(al[mt], sAl + off);
      }
      uint32_t bhf[2][4], blf[2][4];
#pragma unroll
      for (int nt2 = 0; nt2 < 2; nt2++) {
        const int row = wn * 32 + nt2 * 16 + lr;
        const uint32_t off =
            (uint32_t)row * 128u + (uint32_t)((chunk ^ (row & 7)) << 4);
        ldsm4(bhf[nt2], sBh + off);
        ldsm4(blf[nt2], sBl + off);
      }
#pragma unroll
      for (int mt = 0; mt < 4; mt++) {
#pragma unroll
        for (int nt = 0; nt < 4; nt++) {
          uint32_t bh2[2] = {bhf[nt >> 1][nt & 1], bhf[nt >> 1][(nt & 1) + 2]};
          uint32_t bl2[2] = {blf[nt >> 1][nt & 1], blf[nt >> 1][(nt & 1) + 2]};
          mma_bf16(acc[mt][nt], ah[mt], bh2);
          mma_bf16(acc[mt][nt], ah[mt], bl2);
          mma_bf16(acc[mt][nt], al[mt], bh2);
        }
      }
    }
    __syncthreads();
  }

  // ---- epilogue: write 64x32 warp region, fp32, optional residual ----
  const int qrow = lane >> 2;
  const int qcol = (lane & 3) * 2;
#pragma unroll
  for (int mt = 0; mt < 4; mt++) {
#pragma unroll
    for (int half = 0; half < 2; half++) {
      const int grow = m0 + wm * 64 + mt * 16 + qrow + half * 8;
      float* crow = C + ((size_t)b * M + grow) * NB;
      const float* rrow =
          RES ? (Res + ((size_t)b * M + grow) * NB) : nullptr;
#pragma unroll
      for (int nt = 0; nt < 4; nt++) {
        const int gcol = n0 + wn * 32 + nt * 8 + qcol;
        float2 v = make_float2(acc[mt][nt][half * 2],
                               acc[mt][nt][half * 2 + 1]);
        if (RES) {
          float2 r = *(const float2*)(rrow + gcol);
          v.x += r.x; v.y += r.y;
        }
        *(float2*)(crow + gcol) = v;
      }
    }
  }
}

// ---------------------------------------------------------------------------
// Split fp32 -> (bf16 hi, bf16 lo), elementwise (weights).
// ---------------------------------------------------------------------------
__global__ void split_bf16(const float* __restrict__ w,
                           __nv_bfloat16* __restrict__ h,
                           __nv_bfloat16* __restrict__ l, int n) {
  int i = blockIdx.x * blockDim.x + threadIdx.x;
  if (i < n) {
    float v = w[i];
    __nv_bfloat16 hi = __float2bfloat16(v);
    h[i] = hi;
    l[i] = __float2bfloat16(v - __bfloat162float(hi));
  }
}

// ---------------------------------------------------------------------------
// Transpose [B][K][4096] fp32 -> [B][4096][K] bf16 hi/lo split.
// grid (4096/32, K/32, B), block (32, 8)
// ---------------------------------------------------------------------------
__global__ void transpose_split(const float* __restrict__ X,
                                __nv_bfloat16* __restrict__ Th,
                                __nv_bfloat16* __restrict__ Tl, int K) {
  __shared__ float t[32][33];
  const int nb = blockIdx.x * 32, kb = blockIdx.y * 32, b = blockIdx.z;
  const int tx = threadIdx.x, ty = threadIdx.y;
  const float* Xb = X + (size_t)b * K * 4096;
#pragma unroll
  for (int j = 0; j < 4; j++)
    t[ty + 8 * j][tx] = Xb[(size_t)(kb + ty + 8 * j) * 4096 + nb + tx];
  __syncthreads();
#pragma unroll
  for (int j = 0; j < 4; j++) {
    float v = t[tx][ty + 8 * j];
    const int n = nb + ty + 8 * j;
    const int k = kb + tx;
    __nv_bfloat16 hi = __float2bfloat16(v);
    const size_t o = ((size_t)b * 4096 + n) * K + k;
    Th[o] = hi;
    Tl[o] = __float2bfloat16(v - __bfloat162float(hi));
  }
}

// ---------------------------------------------------------------------------
// Fused depthwise 5x5 (pad 2) + grouped 1x1 (192 groups, 8 in -> 8 out).
// ---------------------------------------------------------------------------
__global__ __launch_bounds__(256) void dwpw_kernel(
    const float* __restrict__ qkv, const float* __restrict__ w_dw,
    const float* __restrict__ w_pw, float* __restrict__ agg) {
  const int g = blockIdx.x;
  const int r0 = blockIdx.y * 16;
  const int b = blockIdx.z;
  const int tid = threadIdx.x;

  __shared__ float tile[8][20][68];
  __shared__ float wd[8][25];
  __shared__ float wp[64];

  if (tid < 200) {
    int i = tid / 25, t = tid % 25;
    wd[i][t] = w_dw[(size_t)(g * 8 + i) * 25 + t];
  }
  if (tid < 64) wp[tid] = w_pw[(size_t)g * 64 + tid];

  const float* src = qkv + (size_t)(b * 1536 + g * 8) * 4096;
  for (int e = tid; e < 8 * 20 * 68; e += 256) {
    int i = e / (20 * 68);
    int rem = e - i * (20 * 68);
    int ry = rem / 68;
    int rx = rem - ry * 68;
    int gy = r0 + ry - 2;
    int gx = rx - 2;
    float v = 0.f;
    if (gy >= 0 && gy < 64 && gx >= 0 && gx < 64)
      v = src[(size_t)i * 4096 + gy * 64 + gx];
    tile[i][ry][rx] = v;
  }
  __syncthreads();

  float* dst = agg + (size_t)(b * 1536 + g * 8) * 4096;
  for (int p = tid; p < 1024; p += 256) {
    int py = p >> 6;
    int px = p & 63;
    float dwv[8];
#pragma unroll
    for (int i = 0; i < 8; i++) {
      float s = 0.f;
#pragma unroll
      for (int ky = 0; ky < 5; ky++)
#pragma unroll
        for (int kx = 0; kx < 5; kx++)
          s += tile[i][py + ky][px + kx] * wd[i][ky * 5 + kx];
      dwv[i] = s;
    }
    const int off = (r0 + py) * 64 + px;
#pragma unroll
    for (int o = 0; o < 8; o++) {
      float a = 0.f;
#pragma unroll
      for (int i = 0; i < 8; i++) a += wp[o * 8 + i] * dwv[i];
      dst[(size_t)o * 4096 + off] = a;
    }
  }
}

// ---------------------------------------------------------------------------
// Linear attention per head; writes transposed bf16 hi/lo output
// at [B][4096][1024] (pixel-major, channel-contiguous).
// ---------------------------------------------------------------------------
__global__ __launch_bounds__(256) void attn_kernel(
    const float* __restrict__ qkv, const float* __restrict__ agg,
    __nv_bfloat16* __restrict__ oth, __nv_bfloat16* __restrict__ otl) {
  const int bh = blockIdx.x;
  const int b = bh >> 7;
  const int h = bh & 127;
  const float* base = (h < 64)
      ? qkv + (size_t)(b * 1536 + h * 24) * 4096
      : agg + (size_t)(b * 1536 + (h - 64) * 24) * 4096;
  const float* qp = base;
  const float* kp = base + (size_t)8 * 4096;
  const float* vp = base + (size_t)16 * 4096;

  __shared__ float svk[72];
  const int tid = threadIdx.x;
  if (tid < 72) svk[tid] = 0.f;
  __syncthreads();

  float a[72];
#pragma unroll
  for (int t = 0; t < 72; t++) a[t] = 0.f;

  for (int n = tid; n < 4096; n += 256) {
    float kv[8], vv[8];
#pragma unroll
    for (int e = 0; e < 8; e++) kv[e] = fmaxf(kp[(size_t)e * 4096 + n], 0.f);
#pragma unroll
    for (int d = 0; d < 8; d++) vv[d] = vp[(size_t)d * 4096 + n];
#pragma unroll
    for (int d = 0; d < 8; d++)
#pragma unroll
      for (int e = 0; e < 8; e++) a[d * 8 + e] += vv[d] * kv[e];
#pragma unroll
    for (int e = 0; e < 8; e++) a[64 + e] += kv[e];
  }

#pragma unroll
  for (int t = 0; t < 72; t++) {
    float s = a[t];
    s += __shfl_down_sync(0xffffffffu, s, 16);
    s += __shfl_down_sync(0xffffffffu, s, 8);
    s += __shfl_down_sync(0xffffffffu, s, 4);
    s += __shfl_down_sync(0xffffffffu, s, 2);
    s += __shfl_down_sync(0xffffffffu, s, 1);
    if ((tid & 31) == 0) atomicAdd(&svk[t], s);
  }
  __syncthreads();

  float vk[72];
#pragma unroll
  for (int t = 0; t < 72; t++) vk[t] = svk[t];

  for (int n = tid; n < 4096; n += 256) {
    float qv[8];
#pragma unroll
    for (int e = 0; e < 8; e++) qv[e] = fmaxf(qp[(size_t)e * 4096 + n], 0.f);
    float den = EPS;
#pragma unroll
    for (int e = 0; e < 8; e++) den += vk[64 + e] * qv[e];
    float rden = 1.0f / den;
    unsigned short hh[8], ll[8];
#pragma unroll
    for (int d = 0; d < 8; d++) {
      float num = 0.f;
#pragma unroll
      for (int e = 0; e < 8; e++) num += vk[d * 8 + e] * qv[e];
      float v = num * rden;
      __nv_bfloat16 hb = __float2bfloat16(v);
      hh[d] = __bfloat16_as_ushort(hb);
      ll[d] = __bfloat16_as_ushort(
          __float2bfloat16(v - __bfloat162float(hb)));
    }
    const size_t o = ((size_t)b * 4096 + n) * 1024 + (size_t)h * 8;
    uint4 uh, ul;
    uh.x = (uint32_t)hh[0] | ((uint32_t)hh[1] << 16);
    uh.y = (uint32_t)hh[2] | ((uint32_t)hh[3] << 16);
    uh.z = (uint32_t)hh[4] | ((uint32_t)hh[5] << 16);
    uh.w = (uint32_t)hh[6] | ((uint32_t)hh[7] << 16);
    ul.x = (uint32_t)ll[0] | ((uint32_t)ll[1] << 16);
    ul.y = (uint32_t)ll[2] | ((uint32_t)ll[3] << 16);
    ul.z = (uint32_t)ll[4] | ((uint32_t)ll[5] << 16);
    ul.w = (uint32_t)ll[6] | ((uint32_t)ll[7] << 16);
    *(uint4*)(oth + o) = uh;
    *(uint4*)(otl + o) = ul;
  }
}

// ---------------------------------------------------------------------------
extern "C" void kernel_launch(void* const* d_in, const int* in_sizes, int n_in,
                              void* d_out, int out_size) {
  const float* x      = (const float*)d_in[0];
  const float* w_qkv  = (const float*)d_in[1];
  const float* w_dw   = (const float*)d_in[2];
  const float* w_pw   = (const float*)d_in[3];
  const float* w_proj = (const float*)d_in[4];
  float* out = (float*)d_out;

  float *qkv, *agg;
  __nv_bfloat16 *xth, *xtl, *ath, *atl, *wqh, *wql, *wph, *wpl;
  cudaGetSymbolAddress((void**)&qkv, g_qkv);
  cudaGetSymbolAddress((void**)&agg, g_agg);
  cudaGetSymbolAddress((void**)&xth, g_xt_h);
  cudaGetSymbolAddress((void**)&xtl, g_xt_l);
  cudaGetSymbolAddress((void**)&ath, g_at_h);
  cudaGetSymbolAddress((void**)&atl, g_at_l);
  cudaGetSymbolAddress((void**)&wqh, g_wq_h);
  cudaGetSymbolAddress((void**)&wql, g_wq_l);
  cudaGetSymbolAddress((void**)&wph, g_wp_h);
  cudaGetSymbolAddress((void**)&wpl, g_wp_l);

  cudaFuncSetAttribute(gemm_hmma<false>,
                       cudaFuncAttributeMaxDynamicSharedMemorySize,
                       GEMM_SMEM_BYTES);
  cudaFuncSetAttribute(gemm_hmma<true>,
                       cudaFuncAttributeMaxDynamicSharedMemorySize,
                       GEMM_SMEM_BYTES);

  // weight splits (tiny)
  split_bf16<<<(1536 * 512 + 255) / 256, 256>>>(w_qkv, wqh, wql, 1536 * 512);
  split_bf16<<<(512 * 1024 + 255) / 256, 256>>>(w_proj, wph, wpl, 512 * 1024);
  // x -> transposed bf16 split
  transpose_split<<<dim3(128, 16, 4), dim3(32, 8)>>>(x, xth, xtl, 512);
  // 1) qkv = w_qkv @ x  (HMMA bf16x3)
  gemm_hmma<false><<<dim3(12, 32, 4), 256, GEMM_SMEM_BYTES>>>(
      wqh, wql, xth, xtl, nullptr, qkv, 1536, 512);
  // 2) agg = grouped_pw(depthwise5x5(qkv))
  dwpw_kernel<<<dim3(192, 4, 4), 256>>>(qkv, w_dw, w_pw, agg);
  // 3) linear attention -> transposed bf16 split
  attn_kernel<<<512, 256>>>(qkv, agg, ath, atl);
  // 4) out = x + w_proj @ attn  (HMMA bf16x3 + residual)
  gemm_hmma<true><<<dim3(4, 32, 4), 256, GEMM_SMEM_BYTES>>>(
      wph, wpl, ath, atl, x, out, 512, 1024);
}

// round 7
// speedup vs baseline: 2.4980x; 1.3542x over previous
#include <cuda_runtime.h>
#include <cuda_bf16.h>
#include <cstdint>

#define EPS 1e-15f

// ---------------- scratch buffers (no runtime allocation allowed) ----------
__device__ float g_qkv[(size_t)4 * 1536 * 4096];          // fp32 qkv
__device__ float g_agg[(size_t)4 * 1536 * 4096];          // fp32 agg
__device__ __nv_bfloat16 g_xt_h[(size_t)4 * 4096 * 512];  // x transposed, hi
__device__ __nv_bfloat16 g_xt_l[(size_t)4 * 4096 * 512];  // x transposed, lo
__device__ __nv_bfloat16 g_at_h[(size_t)4 * 4096 * 1024]; // attn transposed, hi
__device__ __nv_bfloat16 g_at_l[(size_t)4 * 4096 * 1024]; // attn transposed, lo
__device__ __nv_bfloat16 g_wq_h[1536 * 512];
__device__ __nv_bfloat16 g_wq_l[1536 * 512];
__device__ __nv_bfloat16 g_wp_h[512 * 1024];
__device__ __nv_bfloat16 g_wp_l[512 * 1024];

// ---------------- PTX helpers (base-target-safe: HMMA/ldmatrix/cp.async) ----
__device__ __forceinline__ uint32_t smem_u32(const void* p) {
  uint32_t a;
  asm("{ .reg .u64 t; cvta.to.shared.u64 t, %1; cvt.u32.u64 %0, t; }"
      : "=r"(a) : "l"(p));
  return a;
}

__device__ __forceinline__ void cp_async16(uint32_t saddr, const void* gptr) {
  asm volatile("cp.async.cg.shared.global [%0], [%1], 16;" ::
               "r"(saddr), "l"(gptr));
}
__device__ __forceinline__ void cp_commit() {
  asm volatile("cp.async.commit_group;");
}
__device__ __forceinline__ void cp_wait_all() {
  asm volatile("cp.async.wait_group 0;");
}

__device__ __forceinline__ void ldsm4(uint32_t* r, uint32_t addr) {
  asm volatile("ldmatrix.sync.aligned.m8n8.x4.shared.b16 {%0,%1,%2,%3}, [%4];"
               : "=r"(r[0]), "=r"(r[1]), "=r"(r[2]), "=r"(r[3]) : "r"(addr));
}

__device__ __forceinline__ void mma_bf16(float* d, const uint32_t* a,
                                         const uint32_t b0, const uint32_t b1) {
  asm volatile(
      "mma.sync.aligned.m16n8k16.row.col.f32.bf16.bf16.f32 "
      "{%0,%1,%2,%3}, {%4,%5,%6,%7}, {%8,%9}, {%0,%1,%2,%3};"
      : "+f"(d[0]), "+f"(d[1]), "+f"(d[2]), "+f"(d[3])
      : "r"(a[0]), "r"(a[1]), "r"(a[2]), "r"(a[3]), "r"(b0), "r"(b1));
}

// ---------------------------------------------------------------------------
// bf16x3 split GEMM on HMMA (mma.sync m16n8k16).
// C[b] (M x 4096 fp32) = A (M x K) * Bt[b]^T, A = Ah+Al, Bt = Bh+Bl,
// product = Ah*Bh + Ah*Bl + Al*Bh (fp32 accumulate).
// A row-major [M][K]; Bt stored [4096][K] (K contiguous).
// CTA tile 128x128, K-chunk 64, double-buffered cp.async smem.
// 8 warps: 2 (M) x 4 (N); warp tile 64x32.
// MMA issue is TERM-MAJOR so consecutive MMAs never share an accumulator
// (RAW distance 16 instead of 1).
// ---------------------------------------------------------------------------
#define STAGE_BYTES 65536
#define GEMM_SMEM_BYTES (2 * STAGE_BYTES)

template <bool RES>
__global__ void __launch_bounds__(256, 1) gemm_hmma(
    const __nv_bfloat16* __restrict__ Ah, const __nv_bfloat16* __restrict__ Al,
    const __nv_bfloat16* __restrict__ Bh, const __nv_bfloat16* __restrict__ Bl,
    const float* __restrict__ Res, float* __restrict__ C, int M, int K) {
  extern __shared__ char smem[];
  const uint32_t sbase = smem_u32(smem);

  const int tid = threadIdx.x;
  const int warp = tid >> 5;
  const int lane = tid & 31;
  const int wm = warp >> 2;        // 0..1 (M)
  const int wn = warp & 3;         // 0..3 (N)
  const int m0 = blockIdx.x * 128;
  const int n0 = blockIdx.y * 128;
  const int b = blockIdx.z;
  const int NB = 4096;

  const __nv_bfloat16* Bhb = Bh + (size_t)b * NB * K;
  const __nv_bfloat16* Blb = Bl + (size_t)b * NB * K;

  float acc[4][4][4];
#pragma unroll
  for (int i = 0; i < 4; i++)
#pragma unroll
    for (int j = 0; j < 4; j++)
#pragma unroll
      for (int r = 0; r < 4; r++) acc[i][j][r] = 0.f;

  const int nch = K >> 6;

  // ---- stage loader: 4 tiles (Ah,Al,Bh,Bl), 128 rows x 8 chunks of 16B ----
  const int lrow0 = tid >> 3;      // +32*i
  const int lc = tid & 7;          // chunk 0..7
  auto load_stage = [&](int ch, int s) {
    const int k0 = ch << 6;
    const uint32_t sb = sbase + (uint32_t)s * STAGE_BYTES;
#pragma unroll
    for (int i = 0; i < 4; i++) {
      const int row = lrow0 + 32 * i;
      const uint32_t soff =
          (uint32_t)row * 128u + (uint32_t)((lc ^ (row & 7)) << 4);
      const size_t ga = (size_t)(m0 + row) * K + k0 + lc * 8;
      const size_t gb = (size_t)(n0 + row) * K + k0 + lc * 8;
      cp_async16(sb + 0u * 16384u + soff, Ah + ga);
      cp_async16(sb + 1u * 16384u + soff, Al + ga);
      cp_async16(sb + 2u * 16384u + soff, Bhb + gb);
      cp_async16(sb + 3u * 16384u + soff, Blb + gb);
    }
    cp_commit();
  };

  load_stage(0, 0);

  // ldmatrix lane geometry (same for A and B, all non-transposed):
  // lanes 0-15 -> rows 0-15 (k-half 0), lanes 16-31 -> rows 0-15 (k-half 1)
  const int lr = lane & 15;
  const int kh = lane >> 4;

  for (int ch = 0; ch < nch; ch++) {
    cp_wait_all();
    __syncthreads();
    if (ch + 1 < nch) load_stage(ch + 1, (ch + 1) & 1);

    const uint32_t sb = sbase + (uint32_t)(ch & 1) * STAGE_BYTES;
    const uint32_t sAh = sb, sAl = sb + 16384u;
    const uint32_t sBh = sb + 32768u, sBl = sb + 49152u;

#pragma unroll
    for (int s = 0; s < 4; s++) {
      const int chunk = 2 * s + kh;
      uint32_t ah[4][4], al[4][4];
#pragma unroll
      for (int mt = 0; mt < 4; mt++) {
        const int row = wm * 64 + mt * 16 + lr;
        const uint32_t off =
            (uint32_t)row * 128u + (uint32_t)((chunk ^ (row & 7)) << 4);
        ldsm4(ah[mt], sAh + off);
        ldsm4(al[mt], sAl + off);
      }
      uint32_t bhf[2][4], blf[2][4];
#pragma unroll
      for (int nt2 = 0; nt2 < 2; nt2++) {
        const int row = wn * 32 + nt2 * 16 + lr;
        const uint32_t off =
            (uint32_t)row * 128u + (uint32_t)((chunk ^ (row & 7)) << 4);
        ldsm4(bhf[nt2], sBh + off);
        ldsm4(blf[nt2], sBl + off);
      }
      // term-major: 16 independent MMAs per term, RAW distance 16
#pragma unroll
      for (int mt = 0; mt < 4; mt++)
#pragma unroll
        for (int nt = 0; nt < 4; nt++)
          mma_bf16(acc[mt][nt], ah[mt],
                   bhf[nt >> 1][nt & 1], bhf[nt >> 1][(nt & 1) + 2]);
#pragma unroll
      for (int mt = 0; mt < 4; mt++)
#pragma unroll
        for (int nt = 0; nt < 4; nt++)
          mma_bf16(acc[mt][nt], ah[mt],
                   blf[nt >> 1][nt & 1], blf[nt >> 1][(nt & 1) + 2]);
#pragma unroll
      for (int mt = 0; mt < 4; mt++)
#pragma unroll
        for (int nt = 0; nt < 4; nt++)
          mma_bf16(acc[mt][nt], al[mt],
                   bhf[nt >> 1][nt & 1], bhf[nt >> 1][(nt & 1) + 2]);
    }
    __syncthreads();
  }

  // ---- epilogue: write 64x32 warp region, fp32, optional residual ----
  const int qrow = lane >> 2;
  const int qcol = (lane & 3) * 2;
#pragma unroll
  for (int mt = 0; mt < 4; mt++) {
#pragma unroll
    for (int half = 0; half < 2; half++) {
      const int grow = m0 + wm * 64 + mt * 16 + qrow + half * 8;
      float* crow = C + ((size_t)b * M + grow) * NB;
      const float* rrow =
          RES ? (Res + ((size_t)b * M + grow) * NB) : nullptr;
#pragma unroll
      for (int nt = 0; nt < 4; nt++) {
        const int gcol = n0 + wn * 32 + nt * 8 + qcol;
        float2 v = make_float2(acc[mt][nt][half * 2],
                               acc[mt][nt][half * 2 + 1]);
        if (RES) {
          float2 r = *(const float2*)(rrow + gcol);
          v.x += r.x; v.y += r.y;
        }
        *(float2*)(crow + gcol) = v;
      }
    }
  }
}

// ---------------------------------------------------------------------------
// Split fp32 -> (bf16 hi, bf16 lo), elementwise (weights).
// ---------------------------------------------------------------------------
__global__ void split_bf16(const float* __restrict__ w,
                           __nv_bfloat16* __restrict__ h,
                           __nv_bfloat16* __restrict__ l, int n) {
  int i = blockIdx.x * blockDim.x + threadIdx.x;
  if (i < n) {
    float v = w[i];
    __nv_bfloat16 hi = __float2bfloat16(v);
    h[i] = hi;
    l[i] = __float2bfloat16(v - __bfloat162float(hi));
  }
}

// ---------------------------------------------------------------------------
// Transpose [B][K][4096] fp32 -> [B][4096][K] bf16 hi/lo split.
// grid (4096/32, K/32, B), block (32, 8)
// ---------------------------------------------------------------------------
__global__ void transpose_split(const float* __restrict__ X,
                                __nv_bfloat16* __restrict__ Th,
                                __nv_bfloat16* __restrict__ Tl, int K) {
  __shared__ float t[32][33];
  const int nb = blockIdx.x * 32, kb = blockIdx.y * 32, b = blockIdx.z;
  const int tx = threadIdx.x, ty = threadIdx.y;
  const float* Xb = X + (size_t)b * K * 4096;
#pragma unroll
  for (int j = 0; j < 4; j++)
    t[ty + 8 * j][tx] = Xb[(size_t)(kb + ty + 8 * j) * 4096 + nb + tx];
  __syncthreads();
#pragma unroll
  for (int j = 0; j < 4; j++) {
    float v = t[tx][ty + 8 * j];
    const int n = nb + ty + 8 * j;
    const int k = kb + tx;
    __nv_bfloat16 hi = __float2bfloat16(v);
    const size_t o = ((size_t)b * 4096 + n) * K + k;
    Th[o] = hi;
    Tl[o] = __float2bfloat16(v - __bfloat162float(hi));
  }
}

// ---------------------------------------------------------------------------
// Fused depthwise 5x5 (pad 2) + grouped 1x1 (192 groups, 8 in -> 8 out).
// Each thread owns a 4-tall pixel column: per channel, load an 8x5 window
// once (40 LDS) and emit 4 outputs (vs 100 LDS naive) -> ~2.5x fewer LDS.
// ---------------------------------------------------------------------------
__global__ __launch_bounds__(256) void dwpw_kernel(
    const float* __restrict__ qkv, const float* __restrict__ w_dw,
    const float* __restrict__ w_pw, float* __restrict__ agg) {
  const int g = blockIdx.x;
  const int r0 = blockIdx.y * 16;
  const int b = blockIdx.z;
  const int tid = threadIdx.x;

  __shared__ float tile[8][20][68];
  __shared__ float wd[8][25];
  __shared__ float wp[64];

  if (tid < 200) {
    int i = tid / 25, t = tid % 25;
    wd[i][t] = w_dw[(size_t)(g * 8 + i) * 25 + t];
  }
  if (tid < 64) wp[tid] = w_pw[(size_t)g * 64 + tid];

  const float* src = qkv + (size_t)(b * 1536 + g * 8) * 4096;
  for (int e = tid; e < 8 * 20 * 68; e += 256) {
    int i = e / (20 * 68);
    int rem = e - i * (20 * 68);
    int ry = rem / 68;
    int rx = rem - ry * 68;
    int gy = r0 + ry - 2;
    int gx = rx - 2;
    float v = 0.f;
    if (gy >= 0 && gy < 64 && gx >= 0 && gx < 64)
      v = src[(size_t)i * 4096 + gy * 64 + gx];
    tile[i][ry][rx] = v;
  }
  __syncthreads();

  const int px = tid & 63;
  const int py0 = (tid >> 6) * 4;       // 4 vertical outputs per thread
  float dwv[4][8];
#pragma unroll
  for (int i = 0; i < 8; i++) {
    float win[8][5];
#pragma unroll
    for (int r = 0; r < 8; r++)
#pragma unroll
      for (int c = 0; c < 5; c++) win[r][c] = tile[i][py0 + r][px + c];
#pragma unroll
    for (int p = 0; p < 4; p++) {
      float s = 0.f;
#pragma unroll
      for (int ky = 0; ky < 5; ky++)
#pragma unroll
        for (int kx = 0; kx < 5; kx++)
          s += win[p + ky][kx] * wd[i][ky * 5 + kx];
      dwv[p][i] = s;
    }
  }

  float* dst = agg + (size_t)(b * 1536 + g * 8) * 4096;
#pragma unroll
  for (int o = 0; o < 8; o++) {
#pragma unroll
    for (int p = 0; p < 4; p++) {
      float a = 0.f;
#pragma unroll
      for (int i = 0; i < 8; i++) a += wp[o * 8 + i] * dwv[p][i];
      dst[(size_t)o * 4096 + (r0 + py0 + p) * 64 + px] = a;
    }
  }
}

// ---------------------------------------------------------------------------
// Linear attention per head; writes transposed bf16 hi/lo output
// at [B][4096][1024] (pixel-major, channel-contiguous).
// ---------------------------------------------------------------------------
__global__ __launch_bounds__(256) void attn_kernel(
    const float* __restrict__ qkv, const float* __restrict__ agg,
    __nv_bfloat16* __restrict__ oth, __nv_bfloat16* __restrict__ otl) {
  const int bh = blockIdx.x;
  const int b = bh >> 7;
  const int h = bh & 127;
  const float* base = (h < 64)
      ? qkv + (size_t)(b * 1536 + h * 24) * 4096
      : agg + (size_t)(b * 1536 + (h - 64) * 24) * 4096;
  const float* qp = base;
  const float* kp = base + (size_t)8 * 4096;
  const float* vp = base + (size_t)16 * 4096;

  __shared__ float svk[72];
  const int tid = threadIdx.x;
  if (tid < 72) svk[tid] = 0.f;
  __syncthreads();

  float a[72];
#pragma unroll
  for (int t = 0; t < 72; t++) a[t] = 0.f;

  for (int n = tid; n < 4096; n += 256) {
    float kv[8], vv[8];
#pragma unroll
    for (int e = 0; e < 8; e++) kv[e] = fmaxf(kp[(size_t)e * 4096 + n], 0.f);
#pragma unroll
    for (int d = 0; d < 8; d++) vv[d] = vp[(size_t)d * 4096 + n];
#pragma unroll
    for (int d = 0; d < 8; d++)
#pragma unroll
      for (int e = 0; e < 8; e++) a[d * 8 + e] += vv[d] * kv[e];
#pragma unroll
    for (int e = 0; e < 8; e++) a[64 + e] += kv[e];
  }

#pragma unroll
  for (int t = 0; t < 72; t++) {
    float s = a[t];
    s += __shfl_down_sync(0xffffffffu, s, 16);
    s += __shfl_down_sync(0xffffffffu, s, 8);
    s += __shfl_down_sync(0xffffffffu, s, 4);
    s += __shfl_down_sync(0xffffffffu, s, 2);
    s += __shfl_down_sync(0xffffffffu, s, 1);
    if ((tid & 31) == 0) atomicAdd(&svk[t], s);
  }
  __syncthreads();

  float vk[72];
#pragma unroll
  for (int t = 0; t < 72; t++) vk[t] = svk[t];

  for (int n = tid; n < 4096; n += 256) {
    float qv[8];
#pragma unroll
    for (int e = 0; e < 8; e++) qv[e] = fmaxf(qp[(size_t)e * 4096 + n], 0.f);
    float den = EPS;
#pragma unroll
    for (int e = 0; e < 8; e++) den += vk[64 + e] * qv[e];
    float rden = 1.0f / den;
    unsigned short hh[8], ll[8];
#pragma unroll
    for (int d = 0; d < 8; d++) {
      float num = 0.f;
#pragma unroll
      for (int e = 0; e < 8; e++) num += vk[d * 8 + e] * qv[e];
      float v = num * rden;
      __nv_bfloat16 hb = __float2bfloat16(v);
      hh[d] = __bfloat16_as_ushort(hb);
      ll[d] = __bfloat16_as_ushort(
          __float2bfloat16(v - __bfloat162float(hb)));
    }
    const size_t o = ((size_t)b * 4096 + n) * 1024 + (size_t)h * 8;
    uint4 uh, ul;
    uh.x = (uint32_t)hh[0] | ((uint32_t)hh[1] << 16);
    uh.y = (uint32_t)hh[2] | ((uint32_t)hh[3] << 16);
    uh.z = (uint32_t)hh[4] | ((uint32_t)hh[5] << 16);
    uh.w = (uint32_t)hh[6] | ((uint32_t)hh[7] << 16);
    ul.x = (uint32_t)ll[0] | ((uint32_t)ll[1] << 16);
    ul.y = (uint32_t)ll[2] | ((uint32_t)ll[3] << 16);
    ul.z = (uint32_t)ll[4] | ((uint32_t)ll[5] << 16);
    ul.w = (uint32_t)ll[6] | ((uint32_t)ll[7] << 16);
    *(uint4*)(oth + o) = uh;
    *(uint4*)(otl + o) = ul;
  }
}

// ---------------------------------------------------------------------------
extern "C" void kernel_launch(void* const* d_in, const int* in_sizes, int n_in,
                              void* d_out, int out_size) {
  const float* x      = (const float*)d_in[0];
  const float* w_qkv  = (const float*)d_in[1];
  const float* w_dw   = (const float*)d_in[2];
  const float* w_pw   = (const float*)d_in[3];
  const float* w_proj = (const float*)d_in[4];
  float* out = (float*)d_out;

  float *qkv, *agg;
  __nv_bfloat16 *xth, *xtl, *ath, *atl, *wqh, *wql, *wph, *wpl;
  cudaGetSymbolAddress((void**)&qkv, g_qkv);
  cudaGetSymbolAddress((void**)&agg, g_agg);
  cudaGetSymbolAddress((void**)&xth, g_xt_h);
  cudaGetSymbolAddress((void**)&xtl, g_xt_l);
  cudaGetSymbolAddress((void**)&ath, g_at_h);
  cudaGetSymbolAddress((void**)&atl, g_at_l);
  cudaGetSymbolAddress((void**)&wqh, g_wq_h);
  cudaGetSymbolAddress((void**)&wql, g_wq_l);
  cudaGetSymbolAddress((void**)&wph, g_wp_h);
  cudaGetSymbolAddress((void**)&wpl, g_wp_l);

  cudaFuncSetAttribute(gemm_hmma<false>,
                       cudaFuncAttributeMaxDynamicSharedMemorySize,
                       GEMM_SMEM_BYTES);
  cudaFuncSetAttribute(gemm_hmma<true>,
                       cudaFuncAttributeMaxDynamicSharedMemorySize,
                       GEMM_SMEM_BYTES);

  // weight splits (tiny)
  split_bf16<<<(1536 * 512 + 255) / 256, 256>>>(w_qkv, wqh, wql, 1536 * 512);
  split_bf16<<<(512 * 1024 + 255) / 256, 256>>>(w_proj, wph, wpl, 512 * 1024);
  // x -> transposed bf16 split
  transpose_split<<<dim3(128, 16, 4), dim3(32, 8)>>>(x, xth, xtl, 512);
  // 1) qkv = w_qkv @ x  (HMMA bf16x3)
  gemm_hmma<false><<<dim3(12, 32, 4), 256, GEMM_SMEM_BYTES>>>(
      wqh, wql, xth, xtl, nullptr, qkv, 1536, 512);
  // 2) agg = grouped_pw(depthwise5x5(qkv))
  dwpw_kernel<<<dim3(192, 4, 4), 256>>>(qkv, w_dw, w_pw, agg);
  // 3) linear attention -> transposed bf16 split
  attn_kernel<<<512, 256>>>(qkv, agg, ath, atl);
  // 4) out = x + w_proj @ attn  (HMMA bf16x3 + residual)
  gemm_hmma<true><<<dim3(4, 32, 4), 256, GEMM_SMEM_BYTES>>>(
      wph, wpl, ath, atl, x, out, 512, 1024);
}

// round 8
// speedup vs baseline: 2.7974x; 1.1199x over previous
#include <cuda_runtime.h>
#include <cuda_bf16.h>
#include <cstdint>

#define EPS 1e-15f

// ---------------- scratch buffers (no runtime allocation allowed) ----------
__device__ float g_qkv[(size_t)4 * 1536 * 4096];          // fp32 qkv
__device__ float g_agg[(size_t)4 * 1536 * 4096];          // fp32 agg
__device__ __nv_bfloat16 g_xt_h[(size_t)4 * 4096 * 512];  // x transposed, hi
__device__ __nv_bfloat16 g_xt_l[(size_t)4 * 4096 * 512];  // x transposed, lo
__device__ __nv_bfloat16 g_at_h[(size_t)4 * 4096 * 1024]; // attn transposed, hi
__device__ __nv_bfloat16 g_at_l[(size_t)4 * 4096 * 1024]; // attn transposed, lo
__device__ __nv_bfloat16 g_wq_h[1536 * 512];
__device__ __nv_bfloat16 g_wq_l[1536 * 512];
__device__ __nv_bfloat16 g_wp_h[512 * 1024];
__device__ __nv_bfloat16 g_wp_l[512 * 1024];

// ---------------- PTX helpers (base-target-safe: HMMA/ldmatrix/cp.async) ----
__device__ __forceinline__ uint32_t smem_u32(const void* p) {
  uint32_t a;
  asm("{ .reg .u64 t; cvta.to.shared.u64 t, %1; cvt.u32.u64 %0, t; }"
      : "=r"(a) : "l"(p));
  return a;
}

__device__ __forceinline__ void cp_async16(uint32_t saddr, const void* gptr) {
  asm volatile("cp.async.cg.shared.global [%0], [%1], 16;" ::
               "r"(saddr), "l"(gptr));
}
__device__ __forceinline__ void cp_commit() {
  asm volatile("cp.async.commit_group;");
}
__device__ __forceinline__ void cp_wait_all() {
  asm volatile("cp.async.wait_group 0;");
}

__device__ __forceinline__ void ldsm4(uint32_t* r, uint32_t addr) {
  asm volatile("ldmatrix.sync.aligned.m8n8.x4.shared.b16 {%0,%1,%2,%3}, [%4];"
               : "=r"(r[0]), "=r"(r[1]), "=r"(r[2]), "=r"(r[3]) : "r"(addr));
}

__device__ __forceinline__ void mma_bf16(float* d, const uint32_t* a,
                                         const uint32_t b0, const uint32_t b1) {
  asm volatile(
      "mma.sync.aligned.m16n8k16.row.col.f32.bf16.bf16.f32 "
      "{%0,%1,%2,%3}, {%4,%5,%6,%7}, {%8,%9}, {%0,%1,%2,%3};"
      : "+f"(d[0]), "+f"(d[1]), "+f"(d[2]), "+f"(d[3])
      : "r"(a[0]), "r"(a[1]), "r"(a[2]), "r"(a[3]), "r"(b0), "r"(b1));
}

// ---------------------------------------------------------------------------
// bf16x3 split GEMM on HMMA (mma.sync m16n8k16).
// C[b] (M x 4096 fp32) = A (M x K) * Bt[b]^T, A = Ah+Al, Bt = Bh+Bl,
// product = Ah*Bh + Ah*Bl + Al*Bh (fp32 accumulate).
// A row-major [M][K]; Bt stored [4096][K] (K contiguous).
// CTA tile 128x64 (M x N), K-chunk 64, double-buffered cp.async smem.
// 8 warps: 4 (M) x 2 (N); warp tile 32x32.
// Sized for 2 CTAs/SM (regs <= 128 via launch bounds, smem 96KB/CTA)
// to give 4 warps/SMSP for ldsm->HMMA latency hiding.
// ---------------------------------------------------------------------------
#define STAGE_BYTES 49152           // Ah 16K + Al 16K + Bh 8K + Bl 8K
#define GEMM_SMEM_BYTES (2 * STAGE_BYTES)

template <bool RES>
__global__ void __launch_bounds__(256, 2) gemm_hmma(
    const __nv_bfloat16* __restrict__ Ah, const __nv_bfloat16* __restrict__ Al,
    const __nv_bfloat16* __restrict__ Bh, const __nv_bfloat16* __restrict__ Bl,
    const float* __restrict__ Res, float* __restrict__ C, int M, int K) {
  extern __shared__ char smem[];
  const uint32_t sbase = smem_u32(smem);

  const int tid = threadIdx.x;
  const int warp = tid >> 5;
  const int lane = tid & 31;
  const int wm = warp >> 1;        // 0..3 (M)
  const int wn = warp & 1;         // 0..1 (N)
  const int m0 = blockIdx.x * 128;
  const int by = blockIdx.y;
  const int batch = by >> 6;
  const int n0 = (by & 63) * 64;
  const int NB = 4096;

  const __nv_bfloat16* Bhb = Bh + (size_t)batch * NB * K;
  const __nv_bfloat16* Blb = Bl + (size_t)batch * NB * K;

  float acc[2][4][4];
#pragma unroll
  for (int i = 0; i < 2; i++)
#pragma unroll
    for (int j = 0; j < 4; j++)
#pragma unroll
      for (int r = 0; r < 4; r++) acc[i][j][r] = 0.f;

  const int nch = K >> 6;

  // ---- stage loader: Ah/Al 128 rows, Bh/Bl 64 rows; 8 chunks of 16B/row ---
  const int lrow0 = tid >> 3;      // 0..31
  const int lc = tid & 7;          // chunk 0..7
  auto load_stage = [&](int ch, int s) {
    const int k0 = ch << 6;
    const uint32_t sb = sbase + (uint32_t)s * STAGE_BYTES;
#pragma unroll
    for (int i = 0; i < 4; i++) {
      const int row = lrow0 + 32 * i;
      const uint32_t soff =
          (uint32_t)row * 128u + (uint32_t)((lc ^ (row & 7)) << 4);
      const size_t ga = (size_t)(m0 + row) * K + k0 + lc * 8;
      cp_async16(sb + 0u + soff, Ah + ga);
      cp_async16(sb + 16384u + soff, Al + ga);
    }
#pragma unroll
    for (int i = 0; i < 2; i++) {
      const int row = lrow0 + 32 * i;
      const uint32_t soff =
          (uint32_t)row * 128u + (uint32_t)((lc ^ (row & 7)) << 4);
      const size_t gb = (size_t)(n0 + row) * K + k0 + lc * 8;
      cp_async16(sb + 32768u + soff, Bhb + gb);
      cp_async16(sb + 40960u + soff, Blb + gb);
    }
    cp_commit();
  };

  load_stage(0, 0);

  // ldmatrix lane geometry: lanes 0-15 -> rows 0-15 (k-half kh=0),
  // lanes 16-31 -> same rows, k-half 1.
  const int lr = lane & 15;
  const int kh = lane >> 4;

  for (int ch = 0; ch < nch; ch++) {
    cp_wait_all();
    __syncthreads();
    if (ch + 1 < nch) load_stage(ch + 1, (ch + 1) & 1);

    const uint32_t sb = sbase + (uint32_t)(ch & 1) * STAGE_BYTES;
    const uint32_t sAh = sb, sAl = sb + 16384u;
    const uint32_t sBh = sb + 32768u, sBl = sb + 40960u;

#pragma unroll
    for (int s = 0; s < 4; s++) {
      const int chunk = 2 * s + kh;
      uint32_t ah[2][4], al[2][4];
#pragma unroll
      for (int mt = 0; mt < 2; mt++) {
        const int row = wm * 32 + mt * 16 + lr;
        const uint32_t off =
            (uint32_t)row * 128u + (uint32_t)((chunk ^ (row & 7)) << 4);
        ldsm4(ah[mt], sAh + off);
        ldsm4(al[mt], sAl + off);
      }
      uint32_t bhf[2][4], blf[2][4];
#pragma unroll
      for (int nt2 = 0; nt2 < 2; nt2++) {
        const int row = wn * 32 + nt2 * 16 + lr;
        const uint32_t off =
            (uint32_t)row * 128u + (uint32_t)((chunk ^ (row & 7)) << 4);
        ldsm4(bhf[nt2], sBh + off);
        ldsm4(blf[nt2], sBl + off);
      }
      // term-major: 8 independent MMAs per term
#pragma unroll
      for (int mt = 0; mt < 2; mt++)
#pragma unroll
        for (int nt = 0; nt < 4; nt++)
          mma_bf16(acc[mt][nt], ah[mt],
                   bhf[nt >> 1][nt & 1], bhf[nt >> 1][(nt & 1) + 2]);
#pragma unroll
      for (int mt = 0; mt < 2; mt++)
#pragma unroll
        for (int nt = 0; nt < 4; nt++)
          mma_bf16(acc[mt][nt], ah[mt],
                   blf[nt >> 1][nt & 1], blf[nt >> 1][(nt & 1) + 2]);
#pragma unroll
      for (int mt = 0; mt < 2; mt++)
#pragma unroll
        for (int nt = 0; nt < 4; nt++)
          mma_bf16(acc[mt][nt], al[mt],
                   bhf[nt >> 1][nt & 1], bhf[nt >> 1][(nt & 1) + 2]);
    }
    __syncthreads();
  }

  // ---- epilogue: write 32x32 warp region, fp32, optional residual ----
  const int qrow = lane >> 2;
  const int qcol = (lane & 3) * 2;
#pragma unroll
  for (int mt = 0; mt < 2; mt++) {
#pragma unroll
    for (int half = 0; half < 2; half++) {
      const int grow = m0 + wm * 32 + mt * 16 + qrow + half * 8;
      float* crow = C + ((size_t)batch * M + grow) * NB;
      const float* rrow =
          RES ? (Res + ((size_t)batch * M + grow) * NB) : nullptr;
#pragma unroll
      for (int nt = 0; nt < 4; nt++) {
        const int gcol = n0 + wn * 32 + nt * 8 + qcol;
        float2 v = make_float2(acc[mt][nt][half * 2],
                               acc[mt][nt][half * 2 + 1]);
        if (RES) {
          float2 r = *(const float2*)(rrow + gcol);
          v.x += r.x; v.y += r.y;
        }
        *(float2*)(crow + gcol) = v;
      }
    }
  }
}

// ---------------------------------------------------------------------------
// Split fp32 -> (bf16 hi, bf16 lo), elementwise (weights).
// ---------------------------------------------------------------------------
__global__ void split_bf16(const float* __restrict__ w,
                           __nv_bfloat16* __restrict__ h,
                           __nv_bfloat16* __restrict__ l, int n) {
  int i = blockIdx.x * blockDim.x + threadIdx.x;
  if (i < n) {
    float v = w[i];
    __nv_bfloat16 hi = __float2bfloat16(v);
    h[i] = hi;
    l[i] = __float2bfloat16(v - __bfloat162float(hi));
  }
}

// ---------------------------------------------------------------------------
// Transpose [B][K][4096] fp32 -> [B][4096][K] bf16 hi/lo split.
// grid (4096/32, K/32, B), block (32, 8)
// ---------------------------------------------------------------------------
__global__ void transpose_split(const float* __restrict__ X,
                                __nv_bfloat16* __restrict__ Th,
                                __nv_bfloat16* __restrict__ Tl, int K) {
  __shared__ float t[32][33];
  const int nb = blockIdx.x * 32, kb = blockIdx.y * 32, b = blockIdx.z;
  const int tx = threadIdx.x, ty = threadIdx.y;
  const float* Xb = X + (size_t)b * K * 4096;
#pragma unroll
  for (int j = 0; j < 4; j++)
    t[ty + 8 * j][tx] = Xb[(size_t)(kb + ty + 8 * j) * 4096 + nb + tx];
  __syncthreads();
#pragma unroll
  for (int j = 0; j < 4; j++) {
    float v = t[tx][ty + 8 * j];
    const int n = nb + ty + 8 * j;
    const int k = kb + tx;
    __nv_bfloat16 hi = __float2bfloat16(v);
    const size_t o = ((size_t)b * 4096 + n) * K + k;
    Th[o] = hi;
    Tl[o] = __float2bfloat16(v - __bfloat162float(hi));
  }
}

// ---------------------------------------------------------------------------
// Fused depthwise 5x5 (pad 2) + grouped 1x1 (192 groups, 8 in -> 8 out).
// Each thread owns a 4-tall pixel column: per channel, load an 8x5 window
// once (40 LDS) and emit 4 outputs (vs 100 LDS naive) -> ~2.5x fewer LDS.
// ---------------------------------------------------------------------------
__global__ __launch_bounds__(256) void dwpw_kernel(
    const float* __restrict__ qkv, const float* __restrict__ w_dw,
    const float* __restrict__ w_pw, float* __restrict__ agg) {
  const int g = blockIdx.x;
  const int r0 = blockIdx.y * 16;
  const int b = blockIdx.z;
  const int tid = threadIdx.x;

  __shared__ float tile[8][20][68];
  __shared__ float wd[8][25];
  __shared__ float wp[64];

  if (tid < 200) {
    int i = tid / 25, t = tid % 25;
    wd[i][t] = w_dw[(size_t)(g * 8 + i) * 25 + t];
  }
  if (tid < 64) wp[tid] = w_pw[(size_t)g * 64 + tid];

  const float* src = qkv + (size_t)(b * 1536 + g * 8) * 4096;
  for (int e = tid; e < 8 * 20 * 68; e += 256) {
    int i = e / (20 * 68);
    int rem = e - i * (20 * 68);
    int ry = rem / 68;
    int rx = rem - ry * 68;
    int gy = r0 + ry - 2;
    int gx = rx - 2;
    float v = 0.f;
    if (gy >= 0 && gy < 64 && gx >= 0 && gx < 64)
      v = src[(size_t)i * 4096 + gy * 64 + gx];
    tile[i][ry][rx] = v;
  }
  __syncthreads();

  const int px = tid & 63;
  const int py0 = (tid >> 6) * 4;       // 4 vertical outputs per thread
  float dwv[4][8];
#pragma unroll
  for (int i = 0; i < 8; i++) {
    float win[8][5];
#pragma unroll
    for (int r = 0; r < 8; r++)
#pragma unroll
      for (int c = 0; c < 5; c++) win[r][c] = tile[i][py0 + r][px + c];
#pragma unroll
    for (int p = 0; p < 4; p++) {
      float s = 0.f;
#pragma unroll
      for (int ky = 0; ky < 5; ky++)
#pragma unroll
        for (int kx = 0; kx < 5; kx++)
          s += win[p + ky][kx] * wd[i][ky * 5 + kx];
      dwv[p][i] = s;
    }
  }

  float* dst = agg + (size_t)(b * 1536 + g * 8) * 4096;
#pragma unroll
  for (int o = 0; o < 8; o++) {
#pragma unroll
    for (int p = 0; p < 4; p++) {
      float a = 0.f;
#pragma unroll
      for (int i = 0; i < 8; i++) a += wp[o * 8 + i] * dwv[p][i];
      dst[(size_t)o * 4096 + (r0 + py0 + p) * 64 + px] = a;
    }
  }
}

// ---------------------------------------------------------------------------
// Linear attention per head; writes transposed bf16 hi/lo output
// at [B][4096][1024] (pixel-major, channel-contiguous).
// ---------------------------------------------------------------------------
__global__ __launch_bounds__(256) void attn_kernel(
    const float* __restrict__ qkv, const float* __restrict__ agg,
    __nv_bfloat16* __restrict__ oth, __nv_bfloat16* __restrict__ otl) {
  const int bh = blockIdx.x;
  const int b = bh >> 7;
  const int h = bh & 127;
  const float* base = (h < 64)
      ? qkv + (size_t)(b * 1536 + h * 24) * 4096
      : agg + (size_t)(b * 1536 + (h - 64) * 24) * 4096;
  const float* qp = base;
  const float* kp = base + (size_t)8 * 4096;
  const float* vp = base + (size_t)16 * 4096;

  __shared__ float svk[72];
  const int tid = threadIdx.x;
  if (tid < 72) svk[tid] = 0.f;
  __syncthreads();

  float a[72];
#pragma unroll
  for (int t = 0; t < 72; t++) a[t] = 0.f;

  for (int n = tid; n < 4096; n += 256) {
    float kv[8], vv[8];
#pragma unroll
    for (int e = 0; e < 8; e++) kv[e] = fmaxf(kp[(size_t)e * 4096 + n], 0.f);
#pragma unroll
    for (int d = 0; d < 8; d++) vv[d] = vp[(size_t)d * 4096 + n];
#pragma unroll
    for (int d = 0; d < 8; d++)
#pragma unroll
      for (int e = 0; e < 8; e++) a[d * 8 + e] += vv[d] * kv[e];
#pragma unroll
    for (int e = 0; e < 8; e++) a[64 + e] += kv[e];
  }

#pragma unroll
  for (int t = 0; t < 72; t++) {
    float s = a[t];
    s += __shfl_down_sync(0xffffffffu, s, 16);
    s += __shfl_down_sync(0xffffffffu, s, 8);
    s += __shfl_down_sync(0xffffffffu, s, 4);
    s += __shfl_down_sync(0xffffffffu, s, 2);
    s += __shfl_down_sync(0xffffffffu, s, 1);
    if ((tid & 31) == 0) atomicAdd(&svk[t], s);
  }
  __syncthreads();

  float vk[72];
#pragma unroll
  for (int t = 0; t < 72; t++) vk[t] = svk[t];

  for (int n = tid; n < 4096; n += 256) {
    float qv[8];
#pragma unroll
    for (int e = 0; e < 8; e++) qv[e] = fmaxf(qp[(size_t)e * 4096 + n], 0.f);
    float den = EPS;
#pragma unroll
    for (int e = 0; e < 8; e++) den += vk[64 + e] * qv[e];
    float rden = 1.0f / den;
    unsigned short hh[8], ll[8];
#pragma unroll
    for (int d = 0; d < 8; d++) {
      float num = 0.f;
#pragma unroll
      for (int e = 0; e < 8; e++) num += vk[d * 8 + e] * qv[e];
      float v = num * rden;
      __nv_bfloat16 hb = __float2bfloat16(v);
      hh[d] = __bfloat16_as_ushort(hb);
      ll[d] = __bfloat16_as_ushort(
          __float2bfloat16(v - __bfloat162float(hb)));
    }
    const size_t o = ((size_t)b * 4096 + n) * 1024 + (size_t)h * 8;
    uint4 uh, ul;
    uh.x = (uint32_t)hh[0] | ((uint32_t)hh[1] << 16);
    uh.y = (uint32_t)hh[2] | ((uint32_t)hh[3] << 16);
    uh.z = (uint32_t)hh[4] | ((uint32_t)hh[5] << 16);
    uh.w = (uint32_t)hh[6] | ((uint32_t)hh[7] << 16);
    ul.x = (uint32_t)ll[0] | ((uint32_t)ll[1] << 16);
    ul.y = (uint32_t)ll[2] | ((uint32_t)ll[3] << 16);
    ul.z = (uint32_t)ll[4] | ((uint32_t)ll[5] << 16);
    ul.w = (uint32_t)ll[6] | ((uint32_t)ll[7] << 16);
    *(uint4*)(oth + o) = uh;
    *(uint4*)(otl + o) = ul;
  }
}

// ---------------------------------------------------------------------------
extern "C" void kernel_launch(void* const* d_in, const int* in_sizes, int n_in,
                              void* d_out, int out_size) {
  const float* x      = (const float*)d_in[0];
  const float* w_qkv  = (const float*)d_in[1];
  const float* w_dw   = (const float*)d_in[2];
  const float* w_pw   = (const float*)d_in[3];
  const float* w_proj = (const float*)d_in[4];
  float* out = (float*)d_out;

  float *qkv, *agg;
  __nv_bfloat16 *xth, *xtl, *ath, *atl, *wqh, *wql, *wph, *wpl;
  cudaGetSymbolAddress((void**)&qkv, g_qkv);
  cudaGetSymbolAddress((void**)&agg, g_agg);
  cudaGetSymbolAddress((void**)&xth, g_xt_h);
  cudaGetSymbolAddress((void**)&xtl, g_xt_l);
  cudaGetSymbolAddress((void**)&ath, g_at_h);
  cudaGetSymbolAddress((void**)&atl, g_at_l);
  cudaGetSymbolAddress((void**)&wqh, g_wq_h);
  cudaGetSymbolAddress((void**)&wql, g_wq_l);
  cudaGetSymbolAddress((void**)&wph, g_wp_h);
  cudaGetSymbolAddress((void**)&wpl, g_wp_l);

  cudaFuncSetAttribute(gemm_hmma<false>,
                       cudaFuncAttributeMaxDynamicSharedMemorySize,
                       GEMM_SMEM_BYTES);
  cudaFuncSetAttribute(gemm_hmma<true>,
                       cudaFuncAttributeMaxDynamicSharedMemorySize,
                       GEMM_SMEM_BYTES);

  // weight splits (tiny)
  split_bf16<<<(1536 * 512 + 255) / 256, 256>>>(w_qkv, wqh, wql, 1536 * 512);
  split_bf16<<<(512 * 1024 + 255) / 256, 256>>>(w_proj, wph, wpl, 512 * 1024);
  // x -> transposed bf16 split
  transpose_split<<<dim3(128, 16, 4), dim3(32, 8)>>>(x, xth, xtl, 512);
  // 1) qkv = w_qkv @ x  (HMMA bf16x3); grid.y = 64 n-tiles * 4 batches
  gemm_hmma<false><<<dim3(12, 256), 256, GEMM_SMEM_BYTES>>>(
      wqh, wql, xth, xtl, nullptr, qkv, 1536, 512);
  // 2) agg = grouped_pw(depthwise5x5(qkv))
  dwpw_kernel<<<dim3(192, 4, 4), 256>>>(qkv, w_dw, w_pw, agg);
  // 3) linear attention -> transposed bf16 split
  attn_kernel<<<512, 256>>>(qkv, agg, ath, atl);
  // 4) out = x + w_proj @ attn  (HMMA bf16x3 + residual)
  gemm_hmma<true><<<dim3(4, 256), 256, GEMM_SMEM_BYTES>>>(
      wph, wpl, ath, atl, x, out, 512, 1024);
}

// round 9
// speedup vs baseline: 2.8145x; 1.0061x over previous
#include <cuda_runtime.h>
#include <cuda_bf16.h>
#include <cstdint>

#define EPS 1e-15f

// ---------------- scratch buffers (no runtime allocation allowed) ----------
__device__ float g_qkv[(size_t)4 * 1536 * 4096];          // fp32 qkv
__device__ float g_agg[(size_t)4 * 1536 * 4096];          // fp32 agg
__device__ __nv_bfloat16 g_xt_h[(size_t)4 * 4096 * 512];  // x transposed, hi
__device__ __nv_bfloat16 g_xt_l[(size_t)4 * 4096 * 512];  // x transposed, lo
__device__ __nv_bfloat16 g_at_h[(size_t)4 * 4096 * 1024]; // attn transposed, hi
__device__ __nv_bfloat16 g_at_l[(size_t)4 * 4096 * 1024]; // attn transposed, lo
__device__ __nv_bfloat16 g_wq_h[1536 * 512];
__device__ __nv_bfloat16 g_wq_l[1536 * 512];
__device__ __nv_bfloat16 g_wp_h[512 * 1024];
__device__ __nv_bfloat16 g_wp_l[512 * 1024];

// ---------------- PTX helpers (base-target-safe: HMMA/ldmatrix/cp.async) ----
__device__ __forceinline__ uint32_t smem_u32(const void* p) {
  uint32_t a;
  asm("{ .reg .u64 t; cvta.to.shared.u64 t, %1; cvt.u32.u64 %0, t; }"
      : "=r"(a) : "l"(p));
  return a;
}

__device__ __forceinline__ void cp_async16(uint32_t saddr, const void* gptr) {
  asm volatile("cp.async.cg.shared.global [%0], [%1], 16;" ::
               "r"(saddr), "l"(gptr));
}
__device__ __forceinline__ void cp_commit() {
  asm volatile("cp.async.commit_group;");
}
__device__ __forceinline__ void cp_wait_all() {
  asm volatile("cp.async.wait_group 0;");
}

__device__ __forceinline__ void ldsm4(uint32_t* r, uint32_t addr) {
  asm volatile("ldmatrix.sync.aligned.m8n8.x4.shared.b16 {%0,%1,%2,%3}, [%4];"
               : "=r"(r[0]), "=r"(r[1]), "=r"(r[2]), "=r"(r[3]) : "r"(addr));
}

__device__ __forceinline__ void mma_bf16(float* d, const uint32_t* a,
                                         const uint32_t b0, const uint32_t b1) {
  asm volatile(
      "mma.sync.aligned.m16n8k16.row.col.f32.bf16.bf16.f32 "
      "{%0,%1,%2,%3}, {%4,%5,%6,%7}, {%8,%9}, {%0,%1,%2,%3};"
      : "+f"(d[0]), "+f"(d[1]), "+f"(d[2]), "+f"(d[3])
      : "r"(a[0]), "r"(a[1]), "r"(a[2]), "r"(a[3]), "r"(b0), "r"(b1));
}

// ---------------------------------------------------------------------------
// bf16x3 split GEMM on HMMA (mma.sync m16n8k16).
// C[b] (M x 4096 fp32) = A (M x K) * Bt[b]^T, A = Ah+Al, Bt = Bh+Bl,
// product = Ah*Bh + Ah*Bl + Al*Bh (fp32 accumulate).
// CTA tile 128x64, K-chunk 64, double-buffered cp.async smem, 2 CTAs/SM.
// 8 warps: 4 (M) x 2 (N); warp tile 32x32.
// Fragment loads are software-pipelined against the 3 MMA terms:
//   [ldsm blf,al] term1(ah,bh) [ldsm next ah,bh] term2(ah,blf) term3(al,bh)
// so every ldsm has >=8 MMAs of latency cover. One __syncthreads per chunk.
// ---------------------------------------------------------------------------
#define STAGE_BYTES 49152           // Ah 16K + Al 16K + Bh 8K + Bl 8K
#define GEMM_SMEM_BYTES (2 * STAGE_BYTES)

template <bool RES>
__global__ void __launch_bounds__(256, 2) gemm_hmma(
    const __nv_bfloat16* __restrict__ Ah, const __nv_bfloat16* __restrict__ Al,
    const __nv_bfloat16* __restrict__ Bh, const __nv_bfloat16* __restrict__ Bl,
    const float* __restrict__ Res, float* __restrict__ C, int M, int K) {
  extern __shared__ char smem[];
  const uint32_t sbase = smem_u32(smem);

  const int tid = threadIdx.x;
  const int warp = tid >> 5;
  const int lane = tid & 31;
  const int wm = warp >> 1;        // 0..3 (M)
  const int wn = warp & 1;         // 0..1 (N)
  const int m0 = blockIdx.x * 128;
  const int by = blockIdx.y;
  const int batch = by >> 6;
  const int n0 = (by & 63) * 64;
  const int NB = 4096;

  const __nv_bfloat16* Bhb = Bh + (size_t)batch * NB * K;
  const __nv_bfloat16* Blb = Bl + (size_t)batch * NB * K;

  float acc[2][4][4];
#pragma unroll
  for (int i = 0; i < 2; i++)
#pragma unroll
    for (int j = 0; j < 4; j++)
#pragma unroll
      for (int r = 0; r < 4; r++) acc[i][j][r] = 0.f;

  const int nch = K >> 6;

  // ---- stage loader: Ah/Al 128 rows, Bh/Bl 64 rows; 8 chunks of 16B/row ---
  const int lrow0 = tid >> 3;      // 0..31
  const int lc = tid & 7;          // chunk 0..7
  auto load_stage = [&](int ch, int s) {
    const int k0 = ch << 6;
    const uint32_t sb = sbase + (uint32_t)s * STAGE_BYTES;
#pragma unroll
    for (int i = 0; i < 4; i++) {
      const int row = lrow0 + 32 * i;
      const uint32_t soff =
          (uint32_t)row * 128u + (uint32_t)((lc ^ (row & 7)) << 4);
      const size_t ga = (size_t)(m0 + row) * K + k0 + lc * 8;
      cp_async16(sb + 0u + soff, Ah + ga);
      cp_async16(sb + 16384u + soff, Al + ga);
    }
#pragma unroll
    for (int i = 0; i < 2; i++) {
      const int row = lrow0 + 32 * i;
      const uint32_t soff =
          (uint32_t)row * 128u + (uint32_t)((lc ^ (row & 7)) << 4);
      const size_t gb = (size_t)(n0 + row) * K + k0 + lc * 8;
      cp_async16(sb + 32768u + soff, Bhb + gb);
      cp_async16(sb + 40960u + soff, Blb + gb);
    }
    cp_commit();
  };

  load_stage(0, 0);

  // ldmatrix lane geometry: lanes 0-15 -> rows 0-15 (k-half kh=0),
  // lanes 16-31 -> same rows, k-half 1.
  const int lr = lane & 15;
  const int kh = lane >> 4;
  const int arow0 = wm * 32 + lr;     // + mt*16
  const int brow0 = wn * 32 + lr;     // + nt2*16

  for (int ch = 0; ch < nch; ch++) {
    cp_wait_all();
    __syncthreads();
    if (ch + 1 < nch) load_stage(ch + 1, (ch + 1) & 1);

    const uint32_t sb = sbase + (uint32_t)(ch & 1) * STAGE_BYTES;
    const uint32_t sAh = sb, sAl = sb + 16384u;
    const uint32_t sBh = sb + 32768u, sBl = sb + 40960u;

    uint32_t ah[2][2][4], bh[2][2][4];   // double-buffered across s
    uint32_t al[2][4], bl[2][4];         // single-buffered (loaded per s)

    // preload s=0 primary operands
#pragma unroll
    for (int mt = 0; mt < 2; mt++) {
      const int row = arow0 + mt * 16;
      ldsm4(ah[0][mt],
            sAh + (uint32_t)row * 128u + (uint32_t)((kh ^ (row & 7)) << 4));
    }
#pragma unroll
    for (int nt2 = 0; nt2 < 2; nt2++) {
      const int row = brow0 + nt2 * 16;
      ldsm4(bh[0][nt2],
            sBh + (uint32_t)row * 128u + (uint32_t)((kh ^ (row & 7)) << 4));
    }

#pragma unroll
    for (int s = 0; s < 4; s++) {
      const int cur = s & 1, nxt = cur ^ 1;
      const int chunk = 2 * s + kh;
      // secondary operands for this s (latency covered by term1 below)
#pragma unroll
      for (int nt2 = 0; nt2 < 2; nt2++) {
        const int row = brow0 + nt2 * 16;
        ldsm4(bl[nt2], sBl + (uint32_t)row * 128u +
                           (uint32_t)((chunk ^ (row & 7)) << 4));
      }
#pragma unroll
      for (int mt = 0; mt < 2; mt++) {
        const int row = arow0 + mt * 16;
        ldsm4(al[mt], sAl + (uint32_t)row * 128u +
                          (uint32_t)((chunk ^ (row & 7)) << 4));
      }
      // term1: ah x bh
#pragma unroll
      for (int mt = 0; mt < 2; mt++)
#pragma unroll
        for (int nt = 0; nt < 4; nt++)
          mma_bf16(acc[mt][nt], ah[cur][mt],
                   bh[cur][nt >> 1][nt & 1], bh[cur][nt >> 1][(nt & 1) + 2]);
      // prefetch next s primary operands (covered by term2+term3)
      if (s < 3) {
        const int nchunk = chunk + 2;
#pragma unroll
        for (int mt = 0; mt < 2; mt++) {
          const int row = arow0 + mt * 16;
          ldsm4(ah[nxt][mt], sAh + (uint32_t)row * 128u +
                                 (uint32_t)((nchunk ^ (row & 7)) << 4));
        }
#pragma unroll
        for (int nt2 = 0; nt2 < 2; nt2++) {
          const int row = brow0 + nt2 * 16;
          ldsm4(bh[nxt][nt2], sBh + (uint32_t)row * 128u +
                                  (uint32_t)((nchunk ^ (row & 7)) << 4));
        }
      }
      // term2: ah x bl
#pragma unroll
      for (int mt = 0; mt < 2; mt++)
#pragma unroll
        for (int nt = 0; nt < 4; nt++)
          mma_bf16(acc[mt][nt], ah[cur][mt],
                   bl[nt >> 1][nt & 1], bl[nt >> 1][(nt & 1) + 2]);
      // term3: al x bh
#pragma unroll
      for (int mt = 0; mt < 2; mt++)
#pragma unroll
        for (int nt = 0; nt < 4; nt++)
          mma_bf16(acc[mt][nt], al[mt],
                   bh[cur][nt >> 1][nt & 1], bh[cur][nt >> 1][(nt & 1) + 2]);
    }
    // no trailing __syncthreads: next iteration's top barrier protects the
    // stage buffer before it is overwritten (2-chunk distance).
  }

  // ---- epilogue: write 32x32 warp region, fp32, optional residual ----
  const int qrow = lane >> 2;
  const int qcol = (lane & 3) * 2;
#pragma unroll
  for (int mt = 0; mt < 2; mt++) {
#pragma unroll
    for (int half = 0; half < 2; half++) {
      const int grow = m0 + wm * 32 + mt * 16 + qrow + half * 8;
      float* crow = C + ((size_t)batch * M + grow) * NB;
      const float* rrow =
          RES ? (Res + ((size_t)batch * M + grow) * NB) : nullptr;
#pragma unroll
      for (int nt = 0; nt < 4; nt++) {
        const int gcol = n0 + wn * 32 + nt * 8 + qcol;
        float2 v = make_float2(acc[mt][nt][half * 2],
                               acc[mt][nt][half * 2 + 1]);
        if (RES) {
          float2 r = *(const float2*)(rrow + gcol);
          v.x += r.x; v.y += r.y;
        }
        *(float2*)(crow + gcol) = v;
      }
    }
  }
}

// ---------------------------------------------------------------------------
// Split fp32 -> (bf16 hi, bf16 lo), elementwise (weights).
// ---------------------------------------------------------------------------
__global__ void split_bf16(const float* __restrict__ w,
                           __nv_bfloat16* __restrict__ h,
                           __nv_bfloat16* __restrict__ l, int n) {
  int i = blockIdx.x * blockDim.x + threadIdx.x;
  if (i < n) {
    float v = w[i];
    __nv_bfloat16 hi = __float2bfloat16(v);
    h[i] = hi;
    l[i] = __float2bfloat16(v - __bfloat162float(hi));
  }
}

// ---------------------------------------------------------------------------
// Transpose [B][K][4096] fp32 -> [B][4096][K] bf16 hi/lo split.
// grid (4096/32, K/32, B), block (32, 8)
// ---------------------------------------------------------------------------
__global__ void transpose_split(const float* __restrict__ X,
                                __nv_bfloat16* __restrict__ Th,
                                __nv_bfloat16* __restrict__ Tl, int K) {
  __shared__ float t[32][33];
  const int nb = blockIdx.x * 32, kb = blockIdx.y * 32, b = blockIdx.z;
  const int tx = threadIdx.x, ty = threadIdx.y;
  const float* Xb = X + (size_t)b * K * 4096;
#pragma unroll
  for (int j = 0; j < 4; j++)
    t[ty + 8 * j][tx] = Xb[(size_t)(kb + ty + 8 * j) * 4096 + nb + tx];
  __syncthreads();
#pragma unroll
  for (int j = 0; j < 4; j++) {
    float v = t[tx][ty + 8 * j];
    const int n = nb + ty + 8 * j;
    const int k = kb + tx;
    __nv_bfloat16 hi = __float2bfloat16(v);
    const size_t o = ((size_t)b * 4096 + n) * K + k;
    Th[o] = hi;
    Tl[o] = __float2bfloat16(v - __bfloat162float(hi));
  }
}

// ---------------------------------------------------------------------------
// Fused depthwise 5x5 (pad 2) + grouped 1x1 (192 groups, 8 in -> 8 out).
// Each thread owns a 4-tall pixel column: per channel, load an 8x5 window
// once (40 LDS) and emit 4 outputs (vs 100 LDS naive) -> ~2.5x fewer LDS.
// ---------------------------------------------------------------------------
__global__ __launch_bounds__(256) void dwpw_kernel(
    const float* __restrict__ qkv, const float* __restrict__ w_dw,
    const float* __restrict__ w_pw, float* __restrict__ agg) {
  const int g = blockIdx.x;
  const int r0 = blockIdx.y * 16;
  const int b = blockIdx.z;
  const int tid = threadIdx.x;

  __shared__ float tile[8][20][68];
  __shared__ float wd[8][25];
  __shared__ float wp[64];

  if (tid < 200) {
    int i = tid / 25, t = tid % 25;
    wd[i][t] = w_dw[(size_t)(g * 8 + i) * 25 + t];
  }
  if (tid < 64) wp[tid] = w_pw[(size_t)g * 64 + tid];

  const float* src = qkv + (size_t)(b * 1536 + g * 8) * 4096;
  for (int e = tid; e < 8 * 20 * 68; e += 256) {
    int i = e / (20 * 68);
    int rem = e - i * (20 * 68);
    int ry = rem / 68;
    int rx = rem - ry * 68;
    int gy = r0 + ry - 2;
    int gx = rx - 2;
    float v = 0.f;
    if (gy >= 0 && gy < 64 && gx >= 0 && gx < 64)
      v = src[(size_t)i * 4096 + gy * 64 + gx];
    tile[i][ry][rx] = v;
  }
  __syncthreads();

  const int px = tid & 63;
  const int py0 = (tid >> 6) * 4;       // 4 vertical outputs per thread
  float dwv[4][8];
#pragma unroll
  for (int i = 0; i < 8; i++) {
    float win[8][5];
#pragma unroll
    for (int r = 0; r < 8; r++)
#pragma unroll
      for (int c = 0; c < 5; c++) win[r][c] = tile[i][py0 + r][px + c];
#pragma unroll
    for (int p = 0; p < 4; p++) {
      float s = 0.f;
#pragma unroll
      for (int ky = 0; ky < 5; ky++)
#pragma unroll
        for (int kx = 0; kx < 5; kx++)
          s += win[p + ky][kx] * wd[i][ky * 5 + kx];
      dwv[p][i] = s;
    }
  }

  float* dst = agg + (size_t)(b * 1536 + g * 8) * 4096;
#pragma unroll
  for (int o = 0; o < 8; o++) {
#pragma unroll
    for (int p = 0; p < 4; p++) {
      float a = 0.f;
#pragma unroll
      for (int i = 0; i < 8; i++) a += wp[o * 8 + i] * dwv[p][i];
      dst[(size_t)o * 4096 + (r0 + py0 + p) * 64 + px] = a;
    }
  }
}

// ---------------------------------------------------------------------------
// Linear attention per head; writes transposed bf16 hi/lo output
// at [B][4096][1024] (pixel-major, channel-contiguous).
// ---------------------------------------------------------------------------
__global__ __launch_bounds__(256) void attn_kernel(
    const float* __restrict__ qkv, const float* __restrict__ agg,
    __nv_bfloat16* __restrict__ oth, __nv_bfloat16* __restrict__ otl) {
  const int bh = blockIdx.x;
  const int b = bh >> 7;
  const int h = bh & 127;
  const float* base = (h < 64)
      ? qkv + (size_t)(b * 1536 + h * 24) * 4096
      : agg + (size_t)(b * 1536 + (h - 64) * 24) * 4096;
  const float* qp = base;
  const float* kp = base + (size_t)8 * 4096;
  const float* vp = base + (size_t)16 * 4096;

  __shared__ float svk[72];
  const int tid = threadIdx.x;
  if (tid < 72) svk[tid] = 0.f;
  __syncthreads();

  float a[72];
#pragma unroll
  for (int t = 0; t < 72; t++) a[t] = 0.f;

  for (int n = tid; n < 4096; n += 256) {
    float kv[8], vv[8];
#pragma unroll
    for (int e = 0; e < 8; e++) kv[e] = fmaxf(kp[(size_t)e * 4096 + n], 0.f);
#pragma unroll
    for (int d = 0; d < 8; d++) vv[d] = vp[(size_t)d * 4096 + n];
#pragma unroll
    for (int d = 0; d < 8; d++)
#pragma unroll
      for (int e = 0; e < 8; e++) a[d * 8 + e] += vv[d] * kv[e];
#pragma unroll
    for (int e = 0; e < 8; e++) a[64 + e] += kv[e];
  }

#pragma unroll
  for (int t = 0; t < 72; t++) {
    float s = a[t];
    s += __shfl_down_sync(0xffffffffu, s, 16);
    s += __shfl_down_sync(0xffffffffu, s, 8);
    s += __shfl_down_sync(0xffffffffu, s, 4);
    s += __shfl_down_sync(0xffffffffu, s, 2);
    s += __shfl_down_sync(0xffffffffu, s, 1);
    if ((tid & 31) == 0) atomicAdd(&svk[t], s);
  }
  __syncthreads();

  float vk[72];
#pragma unroll
  for (int t = 0; t < 72; t++) vk[t] = svk[t];

  for (int n = tid; n < 4096; n += 256) {
    float qv[8];
#pragma unroll
    for (int e = 0; e < 8; e++) qv[e] = fmaxf(qp[(size_t)e * 4096 + n], 0.f);
    float den = EPS;
#pragma unroll
    for (int e = 0; e < 8; e++) den += vk[64 + e] * qv[e];
    float rden = 1.0f / den;
    unsigned short hh[8], ll[8];
#pragma unroll
    for (int d = 0; d < 8; d++) {
      float num = 0.f;
#pragma unroll
      for (int e = 0; e < 8; e++) num += vk[d * 8 + e] * qv[e];
      float v = num * rden;
      __nv_bfloat16 hb = __float2bfloat16(v);
      hh[d] = __bfloat16_as_ushort(hb);
      ll[d] = __bfloat16_as_ushort(
          __float2bfloat16(v - __bfloat162float(hb)));
    }
    const size_t o = ((size_t)b * 4096 + n) * 1024 + (size_t)h * 8;
    uint4 uh, ul;
    uh.x = (uint32_t)hh[0] | ((uint32_t)hh[1] << 16);
    uh.y = (uint32_t)hh[2] | ((uint32_t)hh[3] << 16);
    uh.z = (uint32_t)hh[4] | ((uint32_t)hh[5] << 16);
    uh.w = (uint32_t)hh[6] | ((uint32_t)hh[7] << 16);
    ul.x = (uint32_t)ll[0] | ((uint32_t)ll[1] << 16);
    ul.y = (uint32_t)ll[2] | ((uint32_t)ll[3] << 16);
    ul.z = (uint32_t)ll[4] | ((uint32_t)ll[5] << 16);
    ul.w = (uint32_t)ll[6] | ((uint32_t)ll[7] << 16);
    *(uint4*)(oth + o) = uh;
    *(uint4*)(otl + o) = ul;
  }
}

// ---------------------------------------------------------------------------
extern "C" void kernel_launch(void* const* d_in, const int* in_sizes, int n_in,
                              void* d_out, int out_size) {
  const float* x      = (const float*)d_in[0];
  const float* w_qkv  = (const float*)d_in[1];
  const float* w_dw   = (const float*)d_in[2];
  const float* w_pw   = (const float*)d_in[3];
  const float* w_proj = (const float*)d_in[4];
  float* out = (float*)d_out;

  float *qkv, *agg;
  __nv_bfloat16 *xth, *xtl, *ath, *atl, *wqh, *wql, *wph, *wpl;
  cudaGetSymbolAddress((void**)&qkv, g_qkv);
  cudaGetSymbolAddress((void**)&agg, g_agg);
  cudaGetSymbolAddress((void**)&xth, g_xt_h);
  cudaGetSymbolAddress((void**)&xtl, g_xt_l);
  cudaGetSymbolAddress((void**)&ath, g_at_h);
  cudaGetSymbolAddress((void**)&atl, g_at_l);
  cudaGetSymbolAddress((void**)&wqh, g_wq_h);
  cudaGetSymbolAddress((void**)&wql, g_wq_l);
  cudaGetSymbolAddress((void**)&wph, g_wp_h);
  cudaGetSymbolAddress((void**)&wpl, g_wp_l);

  cudaFuncSetAttribute(gemm_hmma<false>,
                       cudaFuncAttributeMaxDynamicSharedMemorySize,
                       GEMM_SMEM_BYTES);
  cudaFuncSetAttribute(gemm_hmma<true>,
                       cudaFuncAttributeMaxDynamicSharedMemorySize,
                       GEMM_SMEM_BYTES);

  // weight splits (tiny)
  split_bf16<<<(1536 * 512 + 255) / 256, 256>>>(w_qkv, wqh, wql, 1536 * 512);
  split_bf16<<<(512 * 1024 + 255) / 256, 256>>>(w_proj, wph, wpl, 512 * 1024);
  // x -> transposed bf16 split
  transpose_split<<<dim3(128, 16, 4), dim3(32, 8)>>>(x, xth, xtl, 512);
  // 1) qkv = w_qkv @ x  (HMMA bf16x3); grid.y = 64 n-tiles * 4 batches
  gemm_hmma<false><<<dim3(12, 256), 256, GEMM_SMEM_BYTES>>>(
      wqh, wql, xth, xtl, nullptr, qkv, 1536, 512);
  // 2) agg = grouped_pw(depthwise5x5(qkv))
  dwpw_kernel<<<dim3(192, 4, 4), 256>>>(qkv, w_dw, w_pw, agg);
  // 3) linear attention -> transposed bf16 split
  attn_kernel<<<512, 256>>>(qkv, agg, ath, atl);
  // 4) out = x + w_proj @ attn  (HMMA bf16x3 + residual)
  gemm_hmma<true><<<dim3(4, 256), 256, GEMM_SMEM_BYTES>>>(
      wph, wpl, ath, atl, x, out, 512, 1024);
}